// round 1
// baseline (speedup 1.0000x reference)
#include <cuda_runtime.h>

#define BB 256
#define TT 2048
#define II 64
#define HH 256

// Persistent scratch for the input projection: 256*2048*256 fp32 = 512MB.
// __device__ global (allowed); zero-initialized at module load, and the
// t >= length region is never written, so reads there are deterministic.
__device__ float g_xp[(size_t)BB * TT * HH];

// ---------------------------------------------------------------------------
// Kernel A: xp[b,t,h] = sum_i x[b,t,i]*W_ih[h,i] + b_ih[h] + b_hh[h], t < len[b]
// Grid: (T/64, B), 256 threads. W_ih row cached in 64 regs/thread.
// ---------------------------------------------------------------------------
__global__ __launch_bounds__(256) void xproj_kernel(
    const float* __restrict__ x,
    const int*   __restrict__ lengths,
    const float* __restrict__ W_ih,
    const float* __restrict__ b_ih,
    const float* __restrict__ b_hh)
{
    extern __shared__ float sm[];
    float* ws = sm;                 // [256][65] padded W_ih stage (conflict-free column read)
    float* xs = sm + 256 * 65;      // [64][64] x tile

    const int b  = blockIdx.y;
    const int t0 = blockIdx.x * 64;
    const int len = lengths[b];
    if (t0 >= len) return;
    const int tcnt = min(64, len - t0);
    const int tid = threadIdx.x;

    for (int idx = tid; idx < HH * II; idx += 256) {
        int h = idx >> 6, i = idx & 63;
        ws[h * 65 + i] = W_ih[idx];
    }
    const float* xbase = x + ((size_t)b * TT + t0) * II;
    for (int idx = tid; idx < tcnt * II; idx += 256) {
        xs[idx] = xbase[idx];
    }
    __syncthreads();

    const int h = tid;
    float w[II];
#pragma unroll
    for (int i = 0; i < II; i++) w[i] = ws[h * 65 + i];
    const float bias = b_ih[h] + b_hh[h];

    float* xpb = g_xp + ((size_t)b * TT + t0) * HH + h;
    const float4* xs4 = (const float4*)xs;

    for (int tt = 0; tt < tcnt; tt++) {
        float acc = bias;
#pragma unroll
        for (int i4 = 0; i4 < II / 4; i4++) {
            float4 xv = xs4[tt * (II / 4) + i4];
            acc = fmaf(xv.x, w[4 * i4 + 0], acc);
            acc = fmaf(xv.y, w[4 * i4 + 1], acc);
            acc = fmaf(xv.z, w[4 * i4 + 2], acc);
            acc = fmaf(xv.w, w[4 * i4 + 3], acc);
        }
        xpb[(size_t)tt * HH] = acc;
    }
}

// ---------------------------------------------------------------------------
// Kernel B: persistent recurrent scan. 128 CTAs x 256 threads, 2 batch rows/CTA.
// Thread (g = tid>>2, c = tid&3): accumulates j in [4g,4g+4) over k-chunk
// k = 4i + c. W^T rows k<192 in smem fp32 (stride 264 floats -> phase-conflict-
// free LDS.128); rows k>=192 live in 64 registers/thread. h stored interleaved
// hint[k] = (h_b0[k], h_b1[k]) for single broadcast LDS.64 per k.
// ---------------------------------------------------------------------------
#define RS 264          // padded row stride (floats): 1056 B == 32 mod 128
#define KSM 192         // k-rows resident in smem

__global__ __launch_bounds__(256, 1) void scan_kernel(
    const float* __restrict__ W_hh,
    const int*   __restrict__ lengths,
    const float* __restrict__ W_fc,
    const float* __restrict__ b_fc,
    float*       __restrict__ out)
{
    extern __shared__ float sm[];
    float* WT_s  = sm;                    // [192][264]
    float* hint  = sm + KSM * RS;         // [256][2] interleaved h
    float* hlast = hint + 512;            // [2][256]
    float* red   = hlast + 512;           // [16]

    const int tid = threadIdx.x;
    const int c = tid & 3;
    const int g = tid >> 2;
    const int j_own = 4 * g + c;
    const int b0 = blockIdx.x * 2, b1 = b0 + 1;
    const int L0 = lengths[b0], L1 = lengths[b1];
    const int Tmax = max(L0, L1);

    // Fill WT_s[k][j] = W_hh[j][k] for k < 192 (coalesced global read).
    for (int idx = tid; idx < HH * HH; idx += 256) {
        int j = idx >> 8, k = idx & 255;
        float v = W_hh[idx];
        if (k < KSM) WT_s[k * RS + j] = v;
    }
    // Register-resident tail rows k in [192,256): this thread's (4 j's, 16 k's).
    float4 wr[16];
#pragma unroll
    for (int ii = 0; ii < 16; ii++) {
        int k = KSM + 4 * ii + c;
        wr[ii].x = __ldg(&W_hh[(4 * g + 0) * HH + k]);
        wr[ii].y = __ldg(&W_hh[(4 * g + 1) * HH + k]);
        wr[ii].z = __ldg(&W_hh[(4 * g + 2) * HH + k]);
        wr[ii].w = __ldg(&W_hh[(4 * g + 3) * HH + k]);
    }
    for (int idx = tid; idx < 512; idx += 256) { hint[idx] = 0.f; hlast[idx] = 0.f; }
    __syncthreads();

    const float* xp0p = g_xp + (size_t)b0 * TT * HH + j_own;
    const float* xp1p = g_xp + (size_t)b1 * TT * HH + j_own;
    const float2* h2 = (const float2*)hint;
    const unsigned base_s = c * RS + 4 * g;   // float index into WT_s for i-loop

    for (int t = 0; t < Tmax; t++) {
        // prefetch xp for this step (consumed ~2k cycles later)
        float xpa = xp0p[(size_t)t * HH];
        float xpb = xp1p[(size_t)t * HH];

        float a0 = 0.f, a1 = 0.f, a2 = 0.f, a3 = 0.f;   // batch b0, j = 4g..4g+3
        float c0 = 0.f, c1 = 0.f, c2 = 0.f, c3 = 0.f;   // batch b1

#pragma unroll
        for (int i = 0; i < 48; i++) {
            int k = 4 * i + c;
            float4 w = *(const float4*)&WT_s[base_s + (unsigned)(4 * i) * RS];
            float2 hh = h2[k];
            a0 = fmaf(w.x, hh.x, a0); a1 = fmaf(w.y, hh.x, a1);
            a2 = fmaf(w.z, hh.x, a2); a3 = fmaf(w.w, hh.x, a3);
            c0 = fmaf(w.x, hh.y, c0); c1 = fmaf(w.y, hh.y, c1);
            c2 = fmaf(w.z, hh.y, c2); c3 = fmaf(w.w, hh.y, c3);
        }
#pragma unroll
        for (int ii = 0; ii < 16; ii++) {
            int k = KSM + 4 * ii + c;
            float4 w = wr[ii];
            float2 hh = h2[k];
            a0 = fmaf(w.x, hh.x, a0); a1 = fmaf(w.y, hh.x, a1);
            a2 = fmaf(w.z, hh.x, a2); a3 = fmaf(w.w, hh.x, a3);
            c0 = fmaf(w.x, hh.y, c0); c1 = fmaf(w.y, hh.y, c1);
            c2 = fmaf(w.z, hh.y, c2); c3 = fmaf(w.w, hh.y, c3);
        }

        // Butterfly sum across the 4 k-split lanes (lane bits 0-1 == c).
#define REDUCE4(v) { v += __shfl_xor_sync(0xffffffffu, v, 1); \
                     v += __shfl_xor_sync(0xffffffffu, v, 2); }
        REDUCE4(a0) REDUCE4(a1) REDUCE4(a2) REDUCE4(a3)
        REDUCE4(c0) REDUCE4(c1) REDUCE4(c2) REDUCE4(c3)
#undef REDUCE4

        float s0 = (c == 0) ? a0 : (c == 1) ? a1 : (c == 2) ? a2 : a3;
        float s1 = (c == 0) ? c0 : (c == 1) ? c1 : (c == 2) ? c2 : c3;
        float h0n = tanhf(s0 + xpa);
        float h1n = tanhf(s1 + xpb);

        __syncthreads();                       // all reads of hint done
        ((float2*)hint)[j_own] = make_float2(h0n, h1n);
        if (t == L0 - 1) hlast[j_own] = h0n;
        if (t == L1 - 1) hlast[HH + j_own] = h1n;
        __syncthreads();                       // new h visible
    }

    // Final FC: out[b] = dot(hlast[b], W_fc) + b_fc
    float wf = W_fc[tid];
#pragma unroll
    for (int bb = 0; bb < 2; bb++) {
        float v = hlast[bb * HH + tid] * wf;
#pragma unroll
        for (int o = 16; o > 0; o >>= 1) v += __shfl_down_sync(0xffffffffu, v, o);
        if ((tid & 31) == 0) red[bb * 8 + (tid >> 5)] = v;
    }
    __syncthreads();
    if (tid < 2) {
        float s = b_fc[0];
#pragma unroll
        for (int w = 0; w < 8; w++) s += red[tid * 8 + w];
        out[b0 + tid] = s;
    }
}

// ---------------------------------------------------------------------------
extern "C" void kernel_launch(void* const* d_in, const int* in_sizes, int n_in,
                              void* d_out, int out_size)
{
    const float* x     = (const float*)d_in[0];
    const int*   lens  = (const int*)  d_in[1];
    const float* W_ih  = (const float*)d_in[2];
    const float* W_hh  = (const float*)d_in[3];
    const float* b_ih  = (const float*)d_in[4];
    const float* b_hh  = (const float*)d_in[5];
    const float* W_fc  = (const float*)d_in[6];
    const float* b_fc  = (const float*)d_in[7];
    float* out = (float*)d_out;

    const int A_SMEM = (256 * 65 + 64 * 64) * 4;                       // 82944 B
    const int B_SMEM = (KSM * RS + 512 + 512 + 16) * 4;                // 206912 B
    cudaFuncSetAttribute(xproj_kernel, cudaFuncAttributeMaxDynamicSharedMemorySize, A_SMEM);
    cudaFuncSetAttribute(scan_kernel,  cudaFuncAttributeMaxDynamicSharedMemorySize, B_SMEM);

    dim3 gA(TT / 64, BB);
    xproj_kernel<<<gA, 256, A_SMEM>>>(x, lens, W_ih, b_ih, b_hh);
    scan_kernel<<<BB / 2, 256, B_SMEM>>>(W_hh, lens, W_fc, b_fc, out);
}

// round 2
// speedup vs baseline: 1.2368x; 1.2368x over previous
#include <cuda_runtime.h>

#define BB 256
#define TT 2048
#define II 64
#define HH 256

// Persistent scratch for the input projection: 256*2048*256 fp32 = 512MB.
// Zero-initialized at load; t >= length region never written -> deterministic.
__device__ float g_xp[(size_t)BB * TT * HH];

// ---------------------------------------------------------------------------
// f32x2 packed-math helpers (SASS FFMA2 path; ptxas only emits via PTX f32x2)
// ---------------------------------------------------------------------------
__device__ __forceinline__ unsigned long long pack2(float lo, float hi) {
    unsigned long long r;
    asm("mov.b64 %0, {%1,%2};" : "=l"(r) : "f"(lo), "f"(hi));
    return r;
}
__device__ __forceinline__ unsigned long long dup2(float v) {
    unsigned long long r;
    asm("mov.b64 %0, {%1,%1};" : "=l"(r) : "f"(v));
    return r;
}
__device__ __forceinline__ void ffma2(unsigned long long& acc,
                                      unsigned long long a, unsigned long long b) {
    asm("fma.rn.f32x2 %0, %1, %2, %0;" : "+l"(acc) : "l"(a), "l"(b));
}
__device__ __forceinline__ float2 unpack2(unsigned long long v) {
    float2 f;
    asm("mov.b64 {%0,%1}, %2;" : "=f"(f.x), "=f"(f.y) : "l"(v));
    return f;
}

// ---------------------------------------------------------------------------
// Kernel A: xp[b,t,h] = sum_i x[b,t,i]*W_ih[h,i] + b_ih[h] + b_hh[h], t < len[b]
// ---------------------------------------------------------------------------
__global__ __launch_bounds__(256) void xproj_kernel(
    const float* __restrict__ x,
    const int*   __restrict__ lengths,
    const float* __restrict__ W_ih,
    const float* __restrict__ b_ih,
    const float* __restrict__ b_hh)
{
    extern __shared__ float sm[];
    float* ws = sm;                 // [256][65]
    float* xs = sm + 256 * 65;      // [64][64]

    const int b  = blockIdx.y;
    const int t0 = blockIdx.x * 64;
    const int len = lengths[b];
    if (t0 >= len) return;
    const int tcnt = min(64, len - t0);
    const int tid = threadIdx.x;

    for (int idx = tid; idx < HH * II; idx += 256) {
        int h = idx >> 6, i = idx & 63;
        ws[h * 65 + i] = W_ih[idx];
    }
    const float* xbase = x + ((size_t)b * TT + t0) * II;
    for (int idx = tid; idx < tcnt * II; idx += 256) {
        xs[idx] = xbase[idx];
    }
    __syncthreads();

    const int h = tid;
    float w[II];
#pragma unroll
    for (int i = 0; i < II; i++) w[i] = ws[h * 65 + i];
    const float bias = b_ih[h] + b_hh[h];

    float* xpb = g_xp + ((size_t)b * TT + t0) * HH + h;
    const float4* xs4 = (const float4*)xs;

    for (int tt = 0; tt < tcnt; tt++) {
        float acc = bias;
#pragma unroll
        for (int i4 = 0; i4 < II / 4; i4++) {
            float4 xv = xs4[tt * (II / 4) + i4];
            acc = fmaf(xv.x, w[4 * i4 + 0], acc);
            acc = fmaf(xv.y, w[4 * i4 + 1], acc);
            acc = fmaf(xv.z, w[4 * i4 + 2], acc);
            acc = fmaf(xv.w, w[4 * i4 + 3], acc);
        }
        xpb[(size_t)tt * HH] = acc;
    }
}

// ---------------------------------------------------------------------------
// Kernel B: persistent recurrent scan, FFMA2 edition.
// 128 CTAs x 256 threads, 2 batch rows/CTA.
// Thread (g=tid>>2, c=tid&3): owns j in [4g,4g+4), k-chunk k = 4i+c.
// W^T rows k<KSM in smem fp32 (stride RS=264 floats -> conflict-free LDS.128);
// rows k>=KSM packed in registers as f32x2 pairs (w_j0,w_j1),(w_j2,w_j3).
// h double-buffered as interleaved float2 (h_b0, h_b1) -> 1 barrier/step.
// ---------------------------------------------------------------------------
#define RS 264
#define KSM 80
#define SMI (KSM / 4)            // 20 smem k-iterations
#define RGI ((HH - KSM) / 4)     // 44 register k-iterations

__global__ __launch_bounds__(256, 1) void scan_kernel(
    const float* __restrict__ W_hh,
    const int*   __restrict__ lengths,
    const float* __restrict__ W_fc,
    const float* __restrict__ b_fc,
    float*       __restrict__ out)
{
    extern __shared__ float sm[];
    float* WT_s  = sm;                      // [KSM][RS]
    float2* hb0  = (float2*)(sm + KSM * RS);        // [256] buffer 0
    float2* hb1  = hb0 + HH;                        // [256] buffer 1
    float* hlast = (float*)(hb1 + HH);              // [2][256]
    float* red   = hlast + 2 * HH;                  // [16]

    const int tid = threadIdx.x;
    const int c = tid & 3;
    const int g = tid >> 2;
    const int j_own = 4 * g + c;
    const int b0 = blockIdx.x * 2, b1 = b0 + 1;
    const int L0 = lengths[b0], L1 = lengths[b1];
    const int Tmax = max(L0, L1);

    // Stage W^T rows k < KSM into smem (coalesced read of W_hh).
    for (int idx = tid; idx < HH * HH; idx += 256) {
        int j = idx >> 8, k = idx & 255;
        float v = W_hh[idx];
        if (k < KSM) WT_s[k * RS + j] = v;
    }
    // Register-resident packed W pairs for k in [KSM, 256).
    unsigned long long wpA[RGI], wpB[RGI];
#pragma unroll
    for (int ii = 0; ii < RGI; ii++) {
        int k = KSM + 4 * ii + c;
        float w0 = __ldg(&W_hh[(4 * g + 0) * HH + k]);
        float w1 = __ldg(&W_hh[(4 * g + 1) * HH + k]);
        float w2 = __ldg(&W_hh[(4 * g + 2) * HH + k]);
        float w3 = __ldg(&W_hh[(4 * g + 3) * HH + k]);
        wpA[ii] = pack2(w0, w1);
        wpB[ii] = pack2(w2, w3);
    }
    hb0[tid] = make_float2(0.f, 0.f);
    if (tid < 2 * HH - 256) ;  // (hb1 fully written at t=0 before first read)
    hlast[tid] = 0.f; hlast[HH + tid] = 0.f;
    __syncthreads();

    const float* xp0p = g_xp + (size_t)b0 * TT * HH + j_own;
    const float* xp1p = g_xp + (size_t)b1 * TT * HH + j_own;
    const unsigned base_s = c * RS + 4 * g;

    for (int t = 0; t < Tmax; t++) {
        const float2* hcur = (t & 1) ? hb1 : hb0;
        float2*       hnxt = (t & 1) ? hb0 : hb1;

        // prefetch xp for this step (hidden under the FMA block)
        float xpa = xp0p[(size_t)t * HH];
        float xpb = xp1p[(size_t)t * HH];

        unsigned long long aA = 0ull, aB = 0ull;   // batch b0: (j0,j1),(j2,j3)
        unsigned long long cA = 0ull, cB = 0ull;   // batch b1

#pragma unroll
        for (int i = 0; i < SMI; i++) {
            ulonglong2 wv = *(const ulonglong2*)&WT_s[base_s + (unsigned)(4 * i) * RS];
            float2 hv = hcur[4 * i + c];
            unsigned long long d0 = dup2(hv.x);
            unsigned long long d1 = dup2(hv.y);
            ffma2(aA, wv.x, d0); ffma2(aB, wv.y, d0);
            ffma2(cA, wv.x, d1); ffma2(cB, wv.y, d1);
        }
#pragma unroll
        for (int ii = 0; ii < RGI; ii++) {
            float2 hv = hcur[KSM + 4 * ii + c];
            unsigned long long d0 = dup2(hv.x);
            unsigned long long d1 = dup2(hv.y);
            ffma2(aA, wpA[ii], d0); ffma2(aB, wpB[ii], d0);
            ffma2(cA, wpA[ii], d1); ffma2(cB, wpB[ii], d1);
        }

        float2 fA = unpack2(aA), fB = unpack2(aB);
        float2 fC = unpack2(cA), fD = unpack2(cB);
        float a0 = fA.x, a1 = fA.y, a2 = fB.x, a3 = fB.y;
        float c0 = fC.x, c1 = fC.y, c2 = fD.x, c3 = fD.y;

        // Butterfly sum across the 4 k-split lanes (lane bits 0-1 == c).
#define REDUCE4(v) { v += __shfl_xor_sync(0xffffffffu, v, 1); \
                     v += __shfl_xor_sync(0xffffffffu, v, 2); }
        REDUCE4(a0) REDUCE4(a1) REDUCE4(a2) REDUCE4(a3)
        REDUCE4(c0) REDUCE4(c1) REDUCE4(c2) REDUCE4(c3)
#undef REDUCE4

        float s0 = (c == 0) ? a0 : (c == 1) ? a1 : (c == 2) ? a2 : a3;
        float s1 = (c == 0) ? c0 : (c == 1) ? c1 : (c == 2) ? c2 : c3;
        float h0n = tanhf(s0 + xpa);
        float h1n = tanhf(s1 + xpb);

        hnxt[j_own] = make_float2(h0n, h1n);
        if (t == L0 - 1) hlast[j_own] = h0n;
        if (t == L1 - 1) hlast[HH + j_own] = h1n;
        __syncthreads();   // writes to hnxt visible; also fences next-iter
                           // writes into hcur against this iter's reads
    }

    // Final FC: out[b] = dot(hlast[b], W_fc) + b_fc
    float wf = W_fc[tid];
#pragma unroll
    for (int bb = 0; bb < 2; bb++) {
        float v = hlast[bb * HH + tid] * wf;
#pragma unroll
        for (int o = 16; o > 0; o >>= 1) v += __shfl_down_sync(0xffffffffu, v, o);
        if ((tid & 31) == 0) red[bb * 8 + (tid >> 5)] = v;
    }
    __syncthreads();
    if (tid < 2) {
        float s = b_fc[0];
#pragma unroll
        for (int w = 0; w < 8; w++) s += red[tid * 8 + w];
        out[b0 + tid] = s;
    }
}

// ---------------------------------------------------------------------------
extern "C" void kernel_launch(void* const* d_in, const int* in_sizes, int n_in,
                              void* d_out, int out_size)
{
    const float* x     = (const float*)d_in[0];
    const int*   lens  = (const int*)  d_in[1];
    const float* W_ih  = (const float*)d_in[2];
    const float* W_hh  = (const float*)d_in[3];
    const float* b_ih  = (const float*)d_in[4];
    const float* b_hh  = (const float*)d_in[5];
    const float* W_fc  = (const float*)d_in[6];
    const float* b_fc  = (const float*)d_in[7];
    float* out = (float*)d_out;

    const int A_SMEM = (256 * 65 + 64 * 64) * 4;                        // 82944 B
    const int B_SMEM = (KSM * RS + 2 * 2 * HH + 2 * HH + 16) * 4;       // ~91.5 KB
    cudaFuncSetAttribute(xproj_kernel, cudaFuncAttributeMaxDynamicSharedMemorySize, A_SMEM);
    cudaFuncSetAttribute(scan_kernel,  cudaFuncAttributeMaxDynamicSharedMemorySize, B_SMEM);

    dim3 gA(TT / 64, BB);
    xproj_kernel<<<gA, 256, A_SMEM>>>(x, lens, W_ih, b_ih, b_hh);
    scan_kernel<<<BB / 2, 256, B_SMEM>>>(W_hh, lens, W_fc, b_fc, out);
}